// round 17
// baseline (speedup 1.0000x reference)
#include <cuda_runtime.h>

#define NSZ   1536
#define NNSZ  (NSZ * NSZ)          // 2,359,296  (== 2304*1024 == 1152*2048)

// ---------------------------------------------------------------------------
// Scratch (device globals -- allocation-free rule). 151 MB BSS.
// ---------------------------------------------------------------------------
__device__ __align__(16) float  g_z[16 * NNSZ];
__device__ double g_sumP[8][16];     // sliced partials (8 copies spread atomics)
__device__ double g_sqP[8][16];
__device__ float  g_scaleA[4][16];   // BN affine: y = z*scale + shift
__device__ float  g_shiftA[4][16];

// ---- packed f32x2 helpers (sm_103a) ---------------------------------------
__device__ __forceinline__ unsigned long long f2fma(unsigned long long a,
                                                    unsigned long long b,
                                                    unsigned long long c) {
    unsigned long long d;
    asm("fma.rn.f32x2 %0, %1, %2, %3;" : "=l"(d) : "l"(a), "l"(b), "l"(c));
    return d;
}
__device__ __forceinline__ unsigned long long f2add(unsigned long long a,
                                                    unsigned long long b) {
    unsigned long long d;
    asm("add.rn.f32x2 %0, %1, %2;" : "=l"(d) : "l"(a), "l"(b));
    return d;
}
__device__ __forceinline__ unsigned long long f2dup(float x) {
    unsigned long long d;
    unsigned u = __float_as_uint(x);
    asm("mov.b64 %0, {%1, %1};" : "=l"(d) : "r"(u));
    return d;
}
__device__ __forceinline__ unsigned long long f2pack(float lo, float hi) {
    unsigned long long d;
    asm("mov.b64 %0, {%1, %2};" : "=l"(d) : "f"(lo), "f"(hi));
    return d;
}
__device__ __forceinline__ float f2lo(unsigned long long a) {
    return __uint_as_float((unsigned)(a & 0xFFFFFFFFull));
}
__device__ __forceinline__ float f2hi(unsigned long long a) {
    return __uint_as_float((unsigned)(a >> 32));
}
// BN-affine + leaky-relu on a packed pair
__device__ __forceinline__ unsigned long long f2bnlrelu(unsigned long long z,
                                                        unsigned long long s,
                                                        unsigned long long h) {
    z = f2fma(z, s, h);
    float lo = f2lo(z), hi = f2hi(z);
    lo = (lo >= 0.f) ? lo : 0.01f * lo;
    hi = (hi >= 0.f) ? hi : 0.01f * hi;
    return f2pack(lo, hi);
}

// ---------------------------------------------------------------------------
// K0: zero stats partials
// ---------------------------------------------------------------------------
__global__ void k_zero() {
    int t = threadIdx.x;
    if (t < 128) {
        ((double*)g_sumP)[t] = 0.0;
        ((double*)g_sqP)[t]  = 0.0;
    }
}

// ---------------------------------------------------------------------------
// K1: adj + layer-1 matmul + bias -> z1 (16 planes) + stats.
// (unchanged from R16 -- f32x2 packed, 4 j-pos/thread, inner unroll 4)
// ---------------------------------------------------------------------------
__global__ void __launch_bounds__(256, 2) k_l1(const float* __restrict__ x,
                                               const float* __restrict__ W1,
                                               const float* __restrict__ b1) {
    __shared__ __align__(16) float sNXjT[64][132];  // 33.8KB, rows 528B
    __shared__ __align__(16) float sXi[8][64];      // 2KB
    __shared__ __align__(16) float sWd[64][32];     // 8KB dup'd weight pairs
    __shared__ float sB[16];
    __shared__ float sRed[8][32];

    const int t  = threadIdx.x;
    const int j0 = blockIdx.x * 128;
    const int i0 = blockIdx.y * 8;

    for (int idx = t; idx < 128 * 64; idx += 256) {
        int jj = idx >> 6, c = idx & 63;
        sNXjT[c][jj] = -x[(j0 + jj) * 64 + c];
    }
    for (int idx = t; idx < 8 * 64; idx += 256) {
        int r = idx >> 6, c = idx & 63;
        sXi[r][c] = x[(i0 + r) * 64 + c];
    }
    for (int idx = t; idx < 64 * 16; idx += 256) {
        int c = idx >> 4, o = idx & 15;
        float w = W1[o * 64 + c];
        sWd[c][2 * o]     = w;
        sWd[c][2 * o + 1] = w;
    }
    if (t < 16) sB[t] = b1[t];
    __syncthreads();

    const int jq   = t & 31;
    const int irow = t >> 5;

    unsigned long long acc0[16], acc1[16];
#pragma unroll
    for (int o = 0; o < 16; o++) { acc0[o] = 0ull; acc1[o] = 0ull; }

    const unsigned long long ABSM = 0x7FFFFFFF7FFFFFFFull;

#pragma unroll 4
    for (int c = 0; c < 64; c++) {
        unsigned long long xid = f2dup(sXi[irow][c]);
        ulonglong2 nx = *(const ulonglong2*)&sNXjT[c][4 * jq];
        unsigned long long d0 = f2add(xid, nx.x) & ABSM;
        unsigned long long d1 = f2add(xid, nx.y) & ABSM;
        const ulonglong2* wrow = (const ulonglong2*)&sWd[c][0];
#pragma unroll
        for (int o2 = 0; o2 < 8; o2++) {
            ulonglong2 wp = wrow[o2];
            acc0[2 * o2]     = f2fma(d0, wp.x, acc0[2 * o2]);
            acc1[2 * o2]     = f2fma(d1, wp.x, acc1[2 * o2]);
            acc0[2 * o2 + 1] = f2fma(d0, wp.y, acc0[2 * o2 + 1]);
            acc1[2 * o2 + 1] = f2fma(d1, wp.y, acc1[2 * o2 + 1]);
        }
    }

    const int p = (i0 + irow) * NSZ + j0 + 4 * jq;
    float lsum[16], lsq[16];
#pragma unroll
    for (int o = 0; o < 16; o++) {
        float b = sB[o];
        float z0 = f2lo(acc0[o]) + b;
        float z1 = f2hi(acc0[o]) + b;
        float z2 = f2lo(acc1[o]) + b;
        float z3 = f2hi(acc1[o]) + b;
        float4 zz = make_float4(z0, z1, z2, z3);
        *(float4*)&g_z[o * NNSZ + p] = zz;
        lsum[o] = (z0 + z1) + (z2 + z3);
        lsq[o]  = (z0 * z0 + z1 * z1) + (z2 * z2 + z3 * z3);
    }

#pragma unroll
    for (int o = 0; o < 16; o++) {
#pragma unroll
        for (int s = 16; s > 0; s >>= 1) {
            lsum[o] += __shfl_xor_sync(0xffffffffu, lsum[o], s);
            lsq[o]  += __shfl_xor_sync(0xffffffffu, lsq[o],  s);
        }
    }
    const int w = t >> 5, lane = t & 31;
    if (lane == 0) {
#pragma unroll
        for (int o = 0; o < 16; o++) { sRed[w][o] = lsum[o]; sRed[w][16 + o] = lsq[o]; }
    }
    __syncthreads();
    if (t < 32) {
        float v = 0.f;
#pragma unroll
        for (int b = 0; b < 8; b++) v += sRed[b][t];
        int slice = (blockIdx.y * 12 + blockIdx.x) & 7;
        if (t < 16) atomicAdd(&g_sumP[slice][t], (double)v);
        else        atomicAdd(&g_sqP[slice][t - 16], (double)v);
    }
}

// ---------------------------------------------------------------------------
// Finalize BN affine; re-zero partials.  1 block, 32 threads.
// ---------------------------------------------------------------------------
__global__ void k_fin(const float* __restrict__ gamma, const float* __restrict__ beta,
                      int layer, int H) {
    __shared__ double ss[16], qq[16];
    int t = threadIdx.x;
    if (t < 16) {
        double s = 0.0, q = 0.0;
        for (int b = 0; b < 8; b++) { s += g_sumP[b][t]; q += g_sqP[b][t]; }
        ss[t] = s; qq[t] = q;
    }
    __syncthreads();
    for (int l = t; l < 128; l += 32) {
        ((double*)g_sumP)[l] = 0.0;
        ((double*)g_sqP)[l]  = 0.0;
    }
    if (t < H) {
        double mean = ss[t] / (double)NNSZ;
        double var  = qq[t] / (double)NNSZ - mean * mean;   // biased variance
        double inv  = 1.0 / sqrt(var + 1e-5);
        float  sc   = (float)((double)gamma[t] * inv);
        g_scaleA[layer][t] = sc;
        g_shiftA[layer][t] = beta[t] - (float)mean * sc;
    }
}

// ---------------------------------------------------------------------------
// Layer-2 (16->16): f32x2 straight-line, now 4 positions/thread (two packed
// pairs).  Each weight LDS.64 feeds 2 FMA2s = 4 positions (LDS/pos halves vs
// R16); SHFL/pos halves.  Live set = h0[16]+h1[16] u64 = 64 regs + stats 32
// ~= 110 -- k_l1's exact proven shape (64-reg u64 arrays under cap 128,
// straight-line).  LDG.128/STG.128 (p = 4t -> 16B aligned).
// grid 2304 x 256thr x 4pos == NNSZ.
// ---------------------------------------------------------------------------
__global__ void __launch_bounds__(256, 2) k_mid1(const float* __restrict__ Wm,
                                                 const float* __restrict__ bias) {
    __shared__ unsigned long long sW2[16][16];   // {w,w} pairs, [o][c]
    __shared__ unsigned long long sS2[16], sH2[16], sB2[16];
    __shared__ float sRed[8][32];
    int t = threadIdx.x;
    {   // 256 threads fill 256 (o,c) weight pairs
        int o = t >> 4, c = t & 15;
        sW2[o][c] = f2dup(Wm[o * 16 + c]);
    }
    if (t < 16) {
        sS2[t] = f2dup(g_scaleA[0][t]);
        sH2[t] = f2dup(g_shiftA[0][t]);
        sB2[t] = f2dup(bias[t]);
    }
    __syncthreads();

    const int p = blockIdx.x * 1024 + 4 * t;     // 4 consecutive positions

    unsigned long long h0[16], h1[16];
#pragma unroll
    for (int c = 0; c < 16; c++) {
        ulonglong2 z2 = *(const ulonglong2*)&g_z[c * NNSZ + p];   // LDG.128
        h0[c] = f2bnlrelu(z2.x, sS2[c], sH2[c]);
        h1[c] = f2bnlrelu(z2.y, sS2[c], sH2[c]);
    }

    float lsum[16], lsq[16];
#pragma unroll
    for (int o = 0; o < 16; o++) {
        unsigned long long a0 = sB2[o], a1 = sB2[o];
#pragma unroll
        for (int c = 0; c < 16; c++) {
            unsigned long long w = sW2[o][c];                     // one LDS.64
            a0 = f2fma(h0[c], w, a0);
            a1 = f2fma(h1[c], w, a1);
        }
        ulonglong2 st; st.x = a0; st.y = a1;
        *(ulonglong2*)&g_z[o * NNSZ + p] = st;                    // STG.128
        float z0 = f2lo(a0), z1 = f2hi(a0), z2 = f2lo(a1), z3 = f2hi(a1);
        lsum[o] = (z0 + z1) + (z2 + z3);
        lsq[o]  = (z0 * z0 + z1 * z1) + (z2 * z2 + z3 * z3);
    }

#pragma unroll
    for (int o = 0; o < 16; o++) {
#pragma unroll
        for (int s = 16; s > 0; s >>= 1) {
            lsum[o] += __shfl_xor_sync(0xffffffffu, lsum[o], s);
            lsq[o]  += __shfl_xor_sync(0xffffffffu, lsq[o],  s);
        }
    }
    int w = t >> 5, lane = t & 31;
    if (lane == 0) {
#pragma unroll
        for (int o = 0; o < 16; o++) { sRed[w][o] = lsum[o]; sRed[w][16 + o] = lsq[o]; }
    }
    __syncthreads();
    if (t < 32) {
        float v = 0.f;
#pragma unroll
        for (int b = 0; b < 8; b++) v += sRed[b][t];
        int slice = blockIdx.x & 7;
        if (t < 16) atomicAdd(&g_sumP[slice][t], (double)v);
        else        atomicAdd(&g_sqP[slice][t - 16], (double)v);
    }
}

// ---------------------------------------------------------------------------
// Later middle layers, PACKED: the proven NPOS=2 loop (R11/R12) with the pair
// packed into u64 -- halves FMA+LDS instruction count at a SMALLER live set
// (h[CI] u64 = CI*2 regs vs float h[2][CI] = same; but single fma stream).
// 4 iterations x 1 pair = 8 positions/thread.  grid 1152 x 256 x 2 x 4 == NNSZ.
// ---------------------------------------------------------------------------
template <int CI, int CO>
__global__ void __launch_bounds__(256, 2) k_midp(const float* __restrict__ Wm,
                                                 const float* __restrict__ bias,
                                                 int layerPrev) {
    __shared__ unsigned long long sW2[CO][CI];
    __shared__ unsigned long long sS2[CI], sH2[CI], sB2[CO];
    __shared__ float sRed[8][32];
    int t = threadIdx.x;
    if (t < CO * CI) {
        int o = t / CI, c = t % CI;
        sW2[o][c] = f2dup(Wm[o * CI + c]);
    }
    if (t < CI) {
        sS2[t] = f2dup(g_scaleA[layerPrev][t]);
        sH2[t] = f2dup(g_shiftA[layerPrev][t]);
    }
    if (t < CO) sB2[t] = f2dup(bias[t]);
    __syncthreads();

    float fsum[CO], fsq[CO];
#pragma unroll
    for (int o = 0; o < CO; o++) { fsum[o] = 0.f; fsq[o] = 0.f; }

    const int base = blockIdx.x * 2048 + 2 * t;    // pair of consecutive pos
#pragma unroll 1
    for (int it = 0; it < 4; it++) {
        const int p = base + it * 512;
        unsigned long long h[CI];
#pragma unroll
        for (int c = 0; c < CI; c++) {
            unsigned long long z = *(const unsigned long long*)&g_z[c * NNSZ + p];
            h[c] = f2bnlrelu(z, sS2[c], sH2[c]);
        }
#pragma unroll
        for (int o = 0; o < CO; o++) {
            unsigned long long acc = sB2[o];
#pragma unroll
            for (int c = 0; c < CI; c++) acc = f2fma(h[c], sW2[o][c], acc);
            *(unsigned long long*)&g_z[o * NNSZ + p] = acc;      // STG.64
            float a0 = f2lo(acc), a1 = f2hi(acc);
            fsum[o] += a0 + a1;
            fsq[o]  += a0 * a0 + a1 * a1;
        }
    }

#pragma unroll
    for (int o = 0; o < CO; o++) {
#pragma unroll
        for (int s = 16; s > 0; s >>= 1) {
            fsum[o] += __shfl_xor_sync(0xffffffffu, fsum[o], s);
            fsq[o]  += __shfl_xor_sync(0xffffffffu, fsq[o],  s);
        }
    }
    int w = t >> 5, lane = t & 31;
    if (lane == 0) {
#pragma unroll
        for (int o = 0; o < CO; o++) { sRed[w][o] = fsum[o]; sRed[w][CO + o] = fsq[o]; }
    }
    __syncthreads();
    if (t < 2 * CO) {
        float v = 0.f;
#pragma unroll
        for (int b = 0; b < 8; b++) v += sRed[b][t];
        int slice = blockIdx.x & 7;
        if (t < CO) atomicAdd(&g_sumP[slice][t], (double)v);
        else        atomicAdd(&g_sqP[slice][t - CO], (double)v);
    }
}

// ---------------------------------------------------------------------------
// Output: BN4 + leaky + dot with W5[8] + b5.  float4 x 4 iters (unchanged).
// ---------------------------------------------------------------------------
__global__ void __launch_bounds__(256, 2) k_out(const float* __restrict__ W5,
                                                const float* __restrict__ b5,
                                                float* __restrict__ out) {
    __shared__ float sS[8], sH[8], sW[8];
    __shared__ float sb;
    int t = threadIdx.x;
    if (t < 8) { sS[t] = g_scaleA[3][t]; sH[t] = g_shiftA[3][t]; sW[t] = W5[t]; }
    if (t == 0) sb = b5[0];
    __syncthreads();
    const int base = blockIdx.x * 4096 + t * 4;
#pragma unroll 1
    for (int it = 0; it < 4; it++) {
        const int p = base + it * 1024;
        float4 a = make_float4(sb, sb, sb, sb);
#pragma unroll
        for (int c = 0; c < 8; c++) {
            float4 z = *(const float4*)&g_z[c * NNSZ + p];
            float sc = sS[c], sh = sH[c], w = sW[c];
            float h;
            h = z.x * sc + sh; h = (h >= 0.f) ? h : 0.01f * h; a.x += w * h;
            h = z.y * sc + sh; h = (h >= 0.f) ? h : 0.01f * h; a.y += w * h;
            h = z.z * sc + sh; h = (h >= 0.f) ? h : 0.01f * h; a.z += w * h;
            h = z.w * sc + sh; h = (h >= 0.f) ? h : 0.01f * h; a.w += w * h;
        }
        *(float4*)&out[p] = a;
    }
}

// ---------------------------------------------------------------------------
// Launch: 10 kernels, graph-capturable, allocation-free, no syncs.
// ---------------------------------------------------------------------------
extern "C" void kernel_launch(void* const* d_in, const int* in_sizes, int n_in,
                              void* d_out, int out_size) {
    (void)in_sizes; (void)n_in; (void)out_size;
    const float* x   = (const float*)d_in[0];
    const float* W1  = (const float*)d_in[1];
    const float* b1  = (const float*)d_in[2];
    const float* g1  = (const float*)d_in[3];
    const float* be1 = (const float*)d_in[4];
    const float* W2  = (const float*)d_in[5];
    const float* b2  = (const float*)d_in[6];
    const float* g2  = (const float*)d_in[7];
    const float* be2 = (const float*)d_in[8];
    const float* W3  = (const float*)d_in[9];
    const float* b3  = (const float*)d_in[10];
    const float* g3  = (const float*)d_in[11];
    const float* be3 = (const float*)d_in[12];
    const float* W4  = (const float*)d_in[13];
    const float* b4  = (const float*)d_in[14];
    const float* g4  = (const float*)d_in[15];
    const float* be4 = (const float*)d_in[16];
    const float* W5  = (const float*)d_in[17];
    const float* b5  = (const float*)d_in[18];
    float* out = (float*)d_out;

    k_zero<<<1, 128>>>();
    k_l1<<<dim3(NSZ / 128, NSZ / 8), 256>>>(x, W1, b1);        // z1 + stats1
    k_fin<<<1, 32>>>(g1, be1, 0, 16);
    k_mid1<<<NNSZ / 1024, 256>>>(W2, b2);                      // z2 + stats2 (4-pos f32x2)
    k_fin<<<1, 32>>>(g2, be2, 1, 16);
    k_midp<16, 8><<<NNSZ / 2048, 256>>>(W3, b3, 1);            // z3 + stats3 (packed)
    k_fin<<<1, 32>>>(g3, be3, 2, 8);
    k_midp<8, 8><<<NNSZ / 2048, 256>>>(W4, b4, 2);             // z4 + stats4 (packed)
    k_fin<<<1, 32>>>(g4, be4, 3, 8);
    k_out<<<NNSZ / 4096, 256>>>(W5, b5, out);
}